// round 4
// baseline (speedup 1.0000x reference)
#include <cuda_runtime.h>
#include <math.h>

// Problem shape (fixed by the dataset).
#define BATCH 1024
#define NBG   256
#define DIM   512
#define DIM4  (DIM/4)              // 128 float4 per row

#define ROWS_PER_WARP   8
#define WARPS_PER_BLOCK 8
#define THREADS_PER_BLOCK (WARPS_PER_BLOCK*32)
#define ROWS_PER_TILE   (ROWS_PER_WARP*WARPS_PER_BLOCK)   // 64
#define N_TILES ((BATCH*NBG)/ROWS_PER_TILE)               // 4096
#define TILES_PER_BLOCK 8
#define GRID (N_TILES/TILES_PER_BLOCK)                    // 512 — all resident, uniform

// Deterministic partial sums (no atomics in the summation -> bitwise
// identical every replay; the atomic below only ELECTS the reducing block).
__device__ float g_partial_bg[GRID];
__device__ float g_partial_pos[BATCH];
__device__ unsigned int g_done_count;   // zero-init; reset by elected block each launch

__device__ __forceinline__ float warp_sum(float v) {
    #pragma unroll
    for (int o = 16; o > 0; o >>= 1)
        v += __shfl_xor_sync(0xFFFFFFFFu, v, o);
    return v;
}

// ---------------------------------------------------------------------------
// Persistent fused kernel: 512 resident blocks, each streams 8 contiguous
// 64-row tiles of bg (2 MB per block), accumulating exp(logit) in registers.
// Tiles [8i, 8i+8) span exactly batches b = 2i, 2i+1; img row + rinv are
// reloaded when b changes (every 4th tile), at which point warp 0 also
// computes the positive logit for that b. Last-to-finish block reduces.
// ---------------------------------------------------------------------------
__global__ void __launch_bounds__(THREADS_PER_BLOCK)
bg_kernel(const float* __restrict__ img, const float* __restrict__ fg,
          const float* __restrict__ bg, float* __restrict__ out)
{
    const int warp = threadIdx.x >> 5;
    const int lane = threadIdx.x & 31;

    float acc = 0.f;            // per-warp (lane-replicated/masked) exp accumulator
    float4 iv[4];
    float rinv = 0.f;

    #pragma unroll 2
    for (int it = 0; it < TILES_PER_BLOCK; it++) {
        const int tile = blockIdx.x * TILES_PER_BLOCK + it;
        const int b = tile >> 2;

        if ((it & 3) == 0) {
            // New batch row: load normalized-img inputs into registers.
            const float4* irow = reinterpret_cast<const float4*>(img + (size_t)b * DIM);
            float nrm = 0.f;
            #pragma unroll
            for (int i = 0; i < 4; i++) {
                iv[i] = irow[lane + 32*i];
                nrm += iv[i].x*iv[i].x + iv[i].y*iv[i].y + iv[i].z*iv[i].z + iv[i].w*iv[i].w;
            }
            nrm = warp_sum(nrm);
            rinv = rsqrtf(nrm);

            // Positive logit for b (warp 0 only; each b hit exactly once chip-wide).
            if (warp == 0) {
                const float4* frow = reinterpret_cast<const float4*>(fg + (size_t)b * DIM);
                float dp = 0.f;
                #pragma unroll
                for (int i = 0; i < 4; i++) {
                    float4 fv = frow[lane + 32*i];
                    dp += fv.x*iv[i].x + fv.y*iv[i].y + fv.z*iv[i].z + fv.w*iv[i].w;
                }
                dp = warp_sum(dp);
                if (lane == 0) g_partial_pos[b] = __expf(dp * rinv);
            }
        }

        const int rowBase = tile * ROWS_PER_TILE + warp * ROWS_PER_WARP;
        const float4* rowp = reinterpret_cast<const float4*>(bg) + (size_t)rowBase * DIM4;

        // Per-lane partial dot for each of the 8 rows (streaming loads).
        float d[ROWS_PER_WARP];
        #pragma unroll
        for (int r = 0; r < ROWS_PER_WARP; r++) {
            const float4* row = rowp + (size_t)r * DIM4;
            float a0 = 0.f;
            #pragma unroll
            for (int i = 0; i < 4; i++) {
                float4 v = __ldcs(&row[lane + 32*i]);
                a0 += v.x*iv[i].x + v.y*iv[i].y + v.z*iv[i].z + v.w*iv[i].w;
            }
            d[r] = a0;
        }

        // Folded butterfly: reduce 8 row-dots across 32 lanes in 9 shuffles.
        #pragma unroll
        for (int i = 0; i < 4; i++) {
            float a  = (lane & 16) ? d[i+4] : d[i];
            float bv = (lane & 16) ? d[i]   : d[i+4];
            d[i] = a + __shfl_xor_sync(0xFFFFFFFFu, bv, 16);
        }
        #pragma unroll
        for (int i = 0; i < 2; i++) {
            float a  = (lane & 8) ? d[i+2] : d[i];
            float bv = (lane & 8) ? d[i]   : d[i+2];
            d[i] = a + __shfl_xor_sync(0xFFFFFFFFu, bv, 8);
        }
        float v;
        {
            float a  = (lane & 4) ? d[1] : d[0];
            float bv = (lane & 4) ? d[0] : d[1];
            v = a + __shfl_xor_sync(0xFFFFFFFFu, bv, 4);
        }
        v += __shfl_xor_sync(0xFFFFFFFFu, v, 2);
        v += __shfl_xor_sync(0xFFFFFFFFu, v, 1);
        // Each lane holds the full dot for its row (replicated x4); mask to 1 copy.
        float e = __expf(v * rinv);
        acc += ((lane & 3) == 0) ? e : 0.f;
    }

    // One block reduction for all 8 tiles.
    acc = warp_sum(acc);
    __shared__ float s[WARPS_PER_BLOCK];
    __shared__ bool s_last;
    if (lane == 0) s[warp] = acc;
    __syncthreads();
    if (threadIdx.x == 0) {
        float t = 0.f;
        #pragma unroll
        for (int w = 0; w < WARPS_PER_BLOCK; w++) t += s[w];
        g_partial_bg[blockIdx.x] = t;
        __threadfence();
        unsigned int c = atomicAdd(&g_done_count, 1u);
        s_last = (c == (unsigned int)(GRID - 1));
    }
    __syncthreads();

    // Last-to-finish block performs the final deterministic reduction.
    if (s_last) {
        const int t = threadIdx.x;
        const float4* pbg  = reinterpret_cast<const float4*>(g_partial_bg);
        const float4* ppos = reinterpret_cast<const float4*>(g_partial_pos);
        float a = 0.f;
        if (t < GRID/4) {                 // 128 float4
            float4 x = pbg[t];
            a = x.x + x.y + x.z + x.w;
        }
        float p = 0.f;
        if (t < BATCH/4) {                // 256 float4
            float4 x = ppos[t];
            p = x.x + x.y + x.z + x.w;
        }
        a = warp_sum(a);
        p = warp_sum(p);
        __shared__ float sb[WARPS_PER_BLOCK], sp[WARPS_PER_BLOCK];
        if (lane == 0) { sb[warp] = a; sp[warp] = p; }
        __syncthreads();
        if (threadIdx.x == 0) {
            float bgsum = 0.f, possum = 0.f;
            #pragma unroll
            for (int w = 0; w < WARPS_PER_BLOCK; w++) { bgsum += sb[w]; possum += sp[w]; }
            out[0] = log1pf(bgsum / possum);
            g_done_count = 0;   // reset for next graph replay
        }
    }
}

extern "C" void kernel_launch(void* const* d_in, const int* in_sizes, int n_in,
                              void* d_out, int out_size)
{
    const float* fg_img = (const float*)d_in[0];   // [B, D]
    const float* fg_pro = (const float*)d_in[1];   // [B, D]
    const float* bg_pro = (const float*)d_in[2];   // [B, N, D]
    float* out = (float*)d_out;

    bg_kernel<<<GRID, THREADS_PER_BLOCK>>>(fg_img, fg_pro, bg_pro, out);
}

// round 5
// speedup vs baseline: 1.0389x; 1.0389x over previous
#include <cuda_runtime.h>
#include <math.h>

// Problem shape (fixed by the dataset).
#define BATCH 1024
#define NBG   256
#define DIM   512
#define DIM4  (DIM/4)              // 128 float4 per row

#define ROWS_PER_WARP   8
#define WARPS_PER_BLOCK 8
#define THREADS_PER_BLOCK (WARPS_PER_BLOCK*32)
#define ROWS_PER_BLOCK  (ROWS_PER_WARP*WARPS_PER_BLOCK)   // 64
#define BG_BLOCKS ((BATCH*NBG)/ROWS_PER_BLOCK)            // 4096
#define MIN_BLOCKS_PER_SM 6                               // force regs <= 42

// Deterministic partial sums (no atomics in the summation -> bitwise
// identical every replay; the atomic below only ELECTS the reducing block).
__device__ float g_partial_bg[BG_BLOCKS];
__device__ float g_partial_pos[BATCH];
__device__ unsigned int g_done_count;   // zero-init; reset by elected block each launch

__device__ __forceinline__ float warp_sum(float v) {
    #pragma unroll
    for (int o = 16; o > 0; o >>= 1)
        v += __shfl_xor_sync(0xFFFFFFFFu, v, o);
    return v;
}

// ---------------------------------------------------------------------------
// Fused kernel: streams bg (512 MB), per-row exp(logit) sums, positive logit
// (warp 0 of every 4th block), final loss in the last-to-finish block.
// Grid 4096 for high occupancy; launch_bounds caps regs for 6 blocks/SM.
// ---------------------------------------------------------------------------
__global__ void __launch_bounds__(THREADS_PER_BLOCK, MIN_BLOCKS_PER_SM)
bg_kernel(const float* __restrict__ img, const float* __restrict__ fg,
          const float* __restrict__ bg, float* __restrict__ out)
{
    const int warp = threadIdx.x >> 5;
    const int lane = threadIdx.x & 31;
    const int rowBase = blockIdx.x * ROWS_PER_BLOCK + warp * ROWS_PER_WARP;
    const int b = blockIdx.x >> 2;   // 4 blocks per batch row; 64 rows/block in one b

    // img row resident in registers for the whole warp's 8 rows.
    const float4* irow = reinterpret_cast<const float4*>(img + (size_t)b * DIM);
    float4 iv[4];
    float nrm = 0.f;
    #pragma unroll
    for (int i = 0; i < 4; i++) {
        iv[i] = irow[lane + 32*i];
        nrm += iv[i].x*iv[i].x + iv[i].y*iv[i].y + iv[i].z*iv[i].z + iv[i].w*iv[i].w;
    }
    nrm = warp_sum(nrm);
    const float rinv = rsqrtf(nrm);

    // Positive logit for batch b (warp 0 of the first block of each b),
    // done up-front so its registers die before the streaming loop.
    if (((blockIdx.x & 3) == 0) && warp == 0) {
        const float4* frow = reinterpret_cast<const float4*>(fg + (size_t)b * DIM);
        float dp = 0.f;
        #pragma unroll
        for (int i = 0; i < 4; i++) {
            float4 fv = frow[lane + 32*i];
            dp += fv.x*iv[i].x + fv.y*iv[i].y + fv.z*iv[i].z + fv.w*iv[i].w;
        }
        dp = warp_sum(dp);
        if (lane == 0) g_partial_pos[b] = __expf(dp * rinv);
    }

    const float4* rowp = reinterpret_cast<const float4*>(bg) + (size_t)rowBase * DIM4;

    // Per-lane partial dot for each of the 8 rows (streaming loads).
    float d[ROWS_PER_WARP];
    #pragma unroll
    for (int r = 0; r < ROWS_PER_WARP; r++) {
        const float4* row = rowp + (size_t)r * DIM4;
        float a0 = 0.f;
        #pragma unroll
        for (int i = 0; i < 4; i++) {
            float4 v = __ldcs(&row[lane + 32*i]);
            a0 += v.x*iv[i].x + v.y*iv[i].y + v.z*iv[i].z + v.w*iv[i].w;
        }
        d[r] = a0;
    }

    // Folded butterfly: reduce 8 row-dots across 32 lanes in 9 shuffles.
    #pragma unroll
    for (int i = 0; i < 4; i++) {
        float a  = (lane & 16) ? d[i+4] : d[i];
        float bv = (lane & 16) ? d[i]   : d[i+4];
        d[i] = a + __shfl_xor_sync(0xFFFFFFFFu, bv, 16);
    }
    #pragma unroll
    for (int i = 0; i < 2; i++) {
        float a  = (lane & 8) ? d[i+2] : d[i];
        float bv = (lane & 8) ? d[i]   : d[i+2];
        d[i] = a + __shfl_xor_sync(0xFFFFFFFFu, bv, 8);
    }
    float v;
    {
        float a  = (lane & 4) ? d[1] : d[0];
        float bv = (lane & 4) ? d[0] : d[1];
        v = a + __shfl_xor_sync(0xFFFFFFFFu, bv, 4);
    }
    v += __shfl_xor_sync(0xFFFFFFFFu, v, 2);
    v += __shfl_xor_sync(0xFFFFFFFFu, v, 1);
    // Each lane holds the full dot for its row (replicated x4); mask to 1 copy.
    float e = __expf(v * rinv);
    float acc = ((lane & 3) == 0) ? e : 0.f;

    // Block reduction of the 8 masked exps per warp.
    acc = warp_sum(acc);
    __shared__ float s[WARPS_PER_BLOCK];
    __shared__ bool s_last;
    if (lane == 0) s[warp] = acc;
    __syncthreads();
    if (threadIdx.x == 0) {
        float t = 0.f;
        #pragma unroll
        for (int w = 0; w < WARPS_PER_BLOCK; w++) t += s[w];
        g_partial_bg[blockIdx.x] = t;
        __threadfence();
        unsigned int c = atomicAdd(&g_done_count, 1u);
        s_last = (c == (unsigned int)(BG_BLOCKS - 1));
    }
    __syncthreads();

    // Last-to-finish block performs the final deterministic reduction.
    if (s_last) {
        const int t = threadIdx.x;
        const float4* pbg  = reinterpret_cast<const float4*>(g_partial_bg);
        const float4* ppos = reinterpret_cast<const float4*>(g_partial_pos);
        float a = 0.f;
        #pragma unroll
        for (int i = 0; i < BG_BLOCKS/4/THREADS_PER_BLOCK; i++) {   // 4 iters
            float4 x = pbg[t + i*THREADS_PER_BLOCK];
            a += x.x + x.y + x.z + x.w;
        }
        float p = 0.f;
        if (t < BATCH/4) {                                           // 256 lanes
            float4 x = ppos[t];
            p = x.x + x.y + x.z + x.w;
        }
        a = warp_sum(a);
        p = warp_sum(p);
        __shared__ float sb[WARPS_PER_BLOCK], sp[WARPS_PER_BLOCK];
        if (lane == 0) { sb[warp] = a; sp[warp] = p; }
        __syncthreads();
        if (threadIdx.x == 0) {
            float bgsum = 0.f, possum = 0.f;
            #pragma unroll
            for (int w = 0; w < WARPS_PER_BLOCK; w++) { bgsum += sb[w]; possum += sp[w]; }
            out[0] = log1pf(bgsum / possum);
            g_done_count = 0;   // reset for next graph replay
        }
    }
}

extern "C" void kernel_launch(void* const* d_in, const int* in_sizes, int n_in,
                              void* d_out, int out_size)
{
    const float* fg_img = (const float*)d_in[0];   // [B, D]
    const float* fg_pro = (const float*)d_in[1];   // [B, D]
    const float* bg_pro = (const float*)d_in[2];   // [B, N, D]
    float* out = (float*)d_out;

    bg_kernel<<<BG_BLOCKS, THREADS_PER_BLOCK>>>(fg_img, fg_pro, bg_pro, out);
}